// round 1
// baseline (speedup 1.0000x reference)
#include <cuda_runtime.h>
#include <cuda_bf16.h>
#include <math.h>

#define BSZ    2
#define ERA    35718
#define HMESH  10242
#define NSRC_F (BSZ*ERA)      // 71436
#define NDST_F (BSZ*HMESH)    // 20484
#define E_E2H  107154
#define E_H2H  61440
#define E_H2E  107154
#define HID    256
#define K_F    102
#define LDA_F  104
#define K_B    260
#define OUTC   96
#define EF_TOT (BSZ*E_E2H)    // 214308
#define EH_TOT (BSZ*E_H2H)    // 122880

// offsets into g_wred (precomputed attention-reduced weight vectors)
#define OFF_WSA_F 0     // 102
#define OFF_WCA_F 104   // 5
#define OFF_WEA_F 112   // 3
#define OFF_WSA_B 128   // 260
#define OFF_WCA_B 392   // 5
#define OFF_WEA_B 400   // 3
#define OFF_WER   408   // 12 : (l*2+h)*4 + k

// ---------------- scratch (static device arrays; no allocation) ----------------
__device__ float g_xin  [NSRC_F*LDA_F];
__device__ float g_Vf   [NSRC_F*HID];
__device__ float g_psrc_f[NSRC_F];
__device__ float g_pctx_f[NDST_F];
__device__ float g_pqs  [NDST_F*2];
__device__ float g_pqd  [NDST_F*2];
__device__ float g_psrc_b[NDST_F];
__device__ float g_pctx_b[NSRC_F];
__device__ float g_maxd [NSRC_F];
__device__ float g_sumd [NSRC_F];
__device__ float g_expv [EH_TOT*2];      // 245760 >= 214308 too
__device__ float g_xlat [NDST_F*HID];
__device__ float g_q    [NDST_F*HID];
__device__ float g_gout [NDST_F*HID];
__device__ float g_h    [NDST_F*HID];
__device__ float g_xpc  [NDST_F*K_B];
__device__ float g_Vb   [NDST_F*OUTC];
__device__ float g_wred [512];

// ---------------- helpers ----------------
__device__ __forceinline__ void atomicMaxFloat(float* addr, float v) {
    int* ia = (int*)addr;
    int old = *ia;
    while (__int_as_float(old) < v) {
        int assumed = old;
        old = atomicCAS(ia, assumed, __float_as_int(v));
        if (old == assumed) break;
    }
}

__device__ __forceinline__ void red_add4(float* p, float a, float b, float c, float d) {
    asm volatile("red.global.add.v4.f32 [%0], {%1,%2,%3,%4};"
                 :: "l"(p), "f"(a), "f"(b), "f"(c), "f"(d) : "memory");
}

__global__ void k_fill(float* p, float v, int n) {
    int i = blockIdx.x * blockDim.x + threadIdx.x;
    if (i < n) p[i] = v;
}

// ---------------- precompute reduced weight vectors ----------------
__global__ void k_precompute(const float* fmWsrc, const float* fmWctx, const float* fmWedge,
                             const float* fmAtt,
                             const float* bmWsrc, const float* bmWctx, const float* bmWedge,
                             const float* bmAtt,
                             const float* gatWe, const float* gatAe) {
    int t = threadIdx.x;  // 512 threads
    if (t < K_F) {
        float a = 0.f;
        for (int j = 0; j < HID; j++) a += fmWsrc[t*HID + j] * fmAtt[j];
        g_wred[OFF_WSA_F + t] = a;
    } else if (t < K_F + 5) {
        int r = t - K_F; float a = 0.f;
        for (int j = 0; j < HID; j++) a += fmWctx[r*HID + j] * fmAtt[j];
        g_wred[OFF_WCA_F + r] = a;
    } else if (t < K_F + 8) {
        int r = t - K_F - 5; float a = 0.f;
        for (int j = 0; j < HID; j++) a += fmWedge[r*HID + j] * fmAtt[j];
        g_wred[OFF_WEA_F + r] = a;
    }
    if (t >= 128 && t < 128 + K_B) {
        int r = t - 128; float a = 0.f;
        for (int j = 0; j < OUTC; j++) a += bmWsrc[r*OUTC + j] * bmAtt[j];
        g_wred[OFF_WSA_B + r] = a;
    }
    if (t >= 400 && t < 405) {
        int r = t - 400; float a = 0.f;
        for (int j = 0; j < OUTC; j++) a += bmWctx[r*OUTC + j] * bmAtt[j];
        g_wred[OFF_WCA_B + r] = a;
    }
    if (t >= 405 && t < 408) {
        int r = t - 405; float a = 0.f;
        for (int j = 0; j < OUTC; j++) a += bmWedge[r*OUTC + j] * bmAtt[j];
        g_wred[OFF_WEA_B + r] = a;
    }
    if (t >= 408 && t < 420) {
        int idx = t - 408;
        int l = idx / 6, h = (idx % 6) / 3, k = idx % 3;
        float a = 0.f;
        for (int dd = 0; dd < 128; dd++)
            a += gatWe[((l*3 + k)*2 + h)*128 + dd] * gatAe[(l*2 + h)*128 + dd];
        g_wred[OFF_WER + (l*2 + h)*4 + k] = a;
    }
}

// ---------------- build x_in (concat + pad) and psrc_f ----------------
__global__ void k_build_xin(const float* __restrict__ x, const float* __restrict__ era_ll) {
    int w = (blockIdx.x * blockDim.x + threadIdx.x) >> 5;
    int lane = threadIdx.x & 31;
    if (w >= NSRC_F) return;
    int node = w % ERA;
    float acc = 0.f;
#pragma unroll
    for (int it = 0; it < 4; it++) {
        int c = lane + it * 32;
        float v = 0.f;
        if (c < 98)       v = x[(size_t)w * 98 + c];
        else if (c < 102) v = era_ll[node * 4 + (c - 98)];
        if (c < LDA_F) g_xin[w * LDA_F + c] = v;
        if (c < 102)   acc += v * g_wred[OFF_WSA_F + c];
    }
    for (int o = 16; o > 0; o >>= 1) acc += __shfl_down_sync(0xffffffff, acc, o);
    if (lane == 0) g_psrc_f[w] = acc;
}

__global__ void k_pctx_f(const float* __restrict__ fm_ctx, const float* __restrict__ h_ll) {
    int d = blockIdx.x * blockDim.x + threadIdx.x;
    if (d >= NDST_F) return;
    int node = d % HMESH;
    float a = fm_ctx[node] * g_wred[OFF_WCA_F];
#pragma unroll
    for (int k = 0; k < 4; k++) a += h_ll[node * 4 + k] * g_wred[OFF_WCA_F + 1 + k];
    g_pctx_f[d] = a;
}

// ---------------- generic fp32 tiled GEMM: C[M,N] = A[M,K(lda)] * B[K,N] ----------------
__global__ __launch_bounds__(256) void k_gemm(const float* __restrict__ A, int lda,
                                              const float* __restrict__ B,
                                              float* __restrict__ C,
                                              int M, int N, int K) {
    __shared__ float As[16 * 128];
    __shared__ float Bs[16 * 128];
    int tid = threadIdx.x;
    int m0 = blockIdx.x * 128;
    int n0 = blockIdx.y * 128;
    int ty = tid >> 4, tx = tid & 15;
    float acc[8][8];
#pragma unroll
    for (int i = 0; i < 8; i++)
#pragma unroll
        for (int j = 0; j < 8; j++) acc[i][j] = 0.f;

    for (int k0 = 0; k0 < K; k0 += 16) {
        {   // load A tile (transposed into As[k][m])
            int am = tid >> 1;
            int ak = (tid & 1) * 8;
            int grow = m0 + am;
#pragma unroll
            for (int i = 0; i < 8; i++) {
                int k = k0 + ak + i;
                float v = (grow < M && k < K) ? A[(size_t)grow * lda + k] : 0.f;
                As[(ak + i) * 128 + am] = v;
            }
        }
        {   // load B tile
            int bk = tid >> 4;
            int bn = (tid & 15) * 8;
            int kg = k0 + bk;
#pragma unroll
            for (int i = 0; i < 8; i++) {
                int gn = n0 + bn + i;
                float v = (kg < K && gn < N) ? B[(size_t)kg * N + gn] : 0.f;
                Bs[bk * 128 + bn + i] = v;
            }
        }
        __syncthreads();
#pragma unroll
        for (int kk = 0; kk < 16; kk++) {
            float4 a0 = *(const float4*)&As[kk * 128 + ty * 8];
            float4 a1 = *(const float4*)&As[kk * 128 + ty * 8 + 4];
            float4 b0 = *(const float4*)&Bs[kk * 128 + tx * 8];
            float4 b1 = *(const float4*)&Bs[kk * 128 + tx * 8 + 4];
            float av[8] = {a0.x, a0.y, a0.z, a0.w, a1.x, a1.y, a1.z, a1.w};
            float bv[8] = {b0.x, b0.y, b0.z, b0.w, b1.x, b1.y, b1.z, b1.w};
#pragma unroll
            for (int i = 0; i < 8; i++)
#pragma unroll
                for (int j = 0; j < 8; j++) acc[i][j] += av[i] * bv[j];
        }
        __syncthreads();
    }
#pragma unroll
    for (int i = 0; i < 8; i++) {
        int row = m0 + ty * 8 + i;
        if (row >= M) continue;
#pragma unroll
        for (int j2 = 0; j2 < 2; j2++) {
            int col = n0 + tx * 8 + j2 * 4;
            if (col + 3 < N) {
                float4 v = make_float4(acc[i][j2*4], acc[i][j2*4+1], acc[i][j2*4+2], acc[i][j2*4+3]);
                *(float4*)&C[(size_t)row * N + col] = v;
            } else {
#pragma unroll
                for (int j = 0; j < 4; j++)
                    if (col + j < N) C[(size_t)row * N + col + j] = acc[i][j2*4 + j];
            }
        }
    }
}

// ---------------- forward mapper edge passes ----------------
__global__ void k_fwd_logits(const int* __restrict__ e2h, const float* __restrict__ ea) {
    int e = blockIdx.x * blockDim.x + threadIdx.x;
    if (e >= EF_TOT) return;
    int eo = e % E_E2H, b = e / E_E2H;
    int s = e2h[eo] + b * ERA;
    int d = e2h[E_E2H + eo] + b * HMESH;
    float pe = ea[eo*3]   * g_wred[OFF_WEA_F]
             + ea[eo*3+1] * g_wred[OFF_WEA_F+1]
             + ea[eo*3+2] * g_wred[OFF_WEA_F+2];
    float l = g_psrc_f[s] + g_pctx_f[d] + pe;
    l = l > 0.f ? l : 0.2f * l;
    g_expv[e] = l;
    atomicMaxFloat(&g_maxd[d], l);
}

__global__ void k_fwd_exp(const int* __restrict__ e2h) {
    int e = blockIdx.x * blockDim.x + threadIdx.x;
    if (e >= EF_TOT) return;
    int eo = e % E_E2H, b = e / E_E2H;
    int d = e2h[E_E2H + eo] + b * HMESH;
    float v = expf(g_expv[e] - g_maxd[d]);
    g_expv[e] = v;
    atomicAdd(&g_sumd[d], v);
}

__global__ void k_fwd_scatter(const int* __restrict__ e2h) {
    int e = (blockIdx.x * blockDim.x + threadIdx.x) >> 5;
    int lane = threadIdx.x & 31;
    if (e >= EF_TOT) return;
    int eo = e % E_E2H, b = e / E_E2H;
    int s = e2h[eo] + b * ERA;
    int d = e2h[E_E2H + eo] + b * HMESH;
    float alpha = g_expv[e] / (g_sumd[d] + 1e-9f);
    int bs = s * HID, bd = d * HID;
#pragma unroll
    for (int c = lane * 4; c < HID; c += 128) {
        float4 v = *(const float4*)&g_Vf[bs + c];
        red_add4(&g_xlat[bd + c], alpha * v.x, alpha * v.y, alpha * v.z, alpha * v.w);
    }
}

// ---------------- GAT passes ----------------
__global__ void k_gat_pq(const float* __restrict__ asrc, const float* __restrict__ adst) {
    int w = (blockIdx.x * blockDim.x + threadIdx.x) >> 5;
    int lane = threadIdx.x & 31;
    if (w >= NDST_F * 2) return;
    int n = w >> 1, h = w & 1;
    const float* qrow = &g_q[n * HID + h * 128];
    float as_ = 0.f, ad_ = 0.f;
#pragma unroll
    for (int it = 0; it < 4; it++) {
        int dd = lane + it * 32;
        float qv = qrow[dd];
        as_ += qv * asrc[h * 128 + dd];
        ad_ += qv * adst[h * 128 + dd];
    }
    for (int o = 16; o > 0; o >>= 1) {
        as_ += __shfl_down_sync(0xffffffff, as_, o);
        ad_ += __shfl_down_sync(0xffffffff, ad_, o);
    }
    if (lane == 0) { g_pqs[w] = as_; g_pqd[w] = ad_; }
}

__global__ void k_gat_logits(const int* __restrict__ h2h, const float* __restrict__ ea, int l) {
    int e = blockIdx.x * blockDim.x + threadIdx.x;
    if (e >= EH_TOT) return;
    int eo = e % E_H2H, b = e / E_H2H;
    int s = h2h[eo] + b * HMESH;
    int d = h2h[E_H2H + eo] + b * HMESH;
#pragma unroll
    for (int h = 0; h < 2; h++) {
        const float* wer = &g_wred[OFF_WER + (l*2 + h)*4];
        float pe = ea[eo*3]*wer[0] + ea[eo*3+1]*wer[1] + ea[eo*3+2]*wer[2];
        float lg = g_pqs[s*2 + h] + g_pqd[d*2 + h] + pe;
        lg = lg > 0.f ? lg : 0.2f * lg;
        g_expv[e*2 + h] = lg;
        atomicMaxFloat(&g_maxd[d*2 + h], lg);
    }
}

__global__ void k_gat_exp(const int* __restrict__ h2h) {
    int e = blockIdx.x * blockDim.x + threadIdx.x;
    if (e >= EH_TOT) return;
    int eo = e % E_H2H, b = e / E_H2H;
    int d = h2h[E_H2H + eo] + b * HMESH;
#pragma unroll
    for (int h = 0; h < 2; h++) {
        float v = expf(g_expv[e*2 + h] - g_maxd[d*2 + h]);
        g_expv[e*2 + h] = v;
        atomicAdd(&g_sumd[d*2 + h], v);
    }
}

__global__ void k_gat_scatter(const int* __restrict__ h2h) {
    int e = (blockIdx.x * blockDim.x + threadIdx.x) >> 5;
    int lane = threadIdx.x & 31;
    if (e >= EH_TOT) return;
    int eo = e % E_H2H, b = e / E_H2H;
    int s = h2h[eo] + b * HMESH;
    int d = h2h[E_H2H + eo] + b * HMESH;
    float a0 = g_expv[e*2]     / (g_sumd[d*2]     + 1e-9f);
    float a1 = g_expv[e*2 + 1] / (g_sumd[d*2 + 1] + 1e-9f);
    int bs = s * HID, bd = d * HID;
#pragma unroll
    for (int c = lane * 4; c < HID; c += 128) {
        float alpha = (c < 128) ? a0 : a1;
        float4 v = *(const float4*)&g_q[bs + c];
        red_add4(&g_gout[bd + c], alpha * v.x, alpha * v.y, alpha * v.z, alpha * v.w);
    }
}

__global__ void k_gelu() {
    int i = blockIdx.x * blockDim.x + threadIdx.x;
    if (i >= NDST_F * HID) return;
    float x = g_gout[i];
    float t = tanhf(0.7978845608f * (x + 0.044715f * x * x * x));
    g_h[i] = 0.5f * x * (1.f + t);
}

// ---------------- decoder prep ----------------
__global__ void k_xpc(const float* __restrict__ h_ll) {
    int n = (blockIdx.x * blockDim.x + threadIdx.x) >> 5;
    int lane = threadIdx.x & 31;
    if (n >= NDST_F) return;
    int node = n % HMESH;
    float acc = 0.f;
#pragma unroll
    for (int it = 0; it < 9; it++) {
        int c = lane + it * 32;
        if (c < K_B) {
            float v;
            if (c < 256) v = g_gout[n * HID + c] + g_xlat[n * HID + c];
            else         v = h_ll[node * 4 + (c - 256)];
            g_xpc[n * K_B + c] = v;
            acc += v * g_wred[OFF_WSA_B + c];
        }
    }
    for (int o = 16; o > 0; o >>= 1) acc += __shfl_down_sync(0xffffffff, acc, o);
    if (lane == 0) g_psrc_b[n] = acc;
}

__global__ void k_pctx_b(const float* __restrict__ bm_ctx, const float* __restrict__ era_ll) {
    int d = blockIdx.x * blockDim.x + threadIdx.x;
    if (d >= NSRC_F) return;
    int node = d % ERA;
    float a = bm_ctx[node] * g_wred[OFF_WCA_B];
#pragma unroll
    for (int k = 0; k < 4; k++) a += era_ll[node * 4 + k] * g_wred[OFF_WCA_B + 1 + k];
    g_pctx_b[d] = a;
}

__global__ void k_bwd_logits(const int* __restrict__ h2e, const float* __restrict__ ea) {
    int e = blockIdx.x * blockDim.x + threadIdx.x;
    if (e >= EF_TOT) return;
    int eo = e % E_H2E, b = e / E_H2E;
    int s = h2e[eo] + b * HMESH;
    int d = h2e[E_H2E + eo] + b * ERA;
    float pe = ea[eo*3]   * g_wred[OFF_WEA_B]
             + ea[eo*3+1] * g_wred[OFF_WEA_B+1]
             + ea[eo*3+2] * g_wred[OFF_WEA_B+2];
    float l = g_psrc_b[s] + g_pctx_b[d] + pe;
    l = l > 0.f ? l : 0.2f * l;
    g_expv[e] = l;
    atomicMaxFloat(&g_maxd[d], l);
}

__global__ void k_bwd_exp(const int* __restrict__ h2e) {
    int e = blockIdx.x * blockDim.x + threadIdx.x;
    if (e >= EF_TOT) return;
    int eo = e % E_H2E, b = e / E_H2E;
    int d = h2e[E_H2E + eo] + b * ERA;
    float v = expf(g_expv[e] - g_maxd[d]);
    g_expv[e] = v;
    atomicAdd(&g_sumd[d], v);
}

__global__ void k_bwd_scatter(const int* __restrict__ h2e, float* __restrict__ out) {
    int e = (blockIdx.x * blockDim.x + threadIdx.x) >> 5;
    int lane = threadIdx.x & 31;
    if (e >= EF_TOT) return;
    int eo = e % E_H2E, b = e / E_H2E;
    int s = h2e[eo] + b * HMESH;
    int d = h2e[E_H2E + eo] + b * ERA;
    float alpha = g_expv[e] / (g_sumd[d] + 1e-9f);
    int c = lane * 4;
    if (c < OUTC) {
        float4 v = *(const float4*)&g_Vb[s * OUTC + c];
        red_add4(&out[d * OUTC + c], alpha * v.x, alpha * v.y, alpha * v.z, alpha * v.w);
    }
}

__global__ void k_final(const float* __restrict__ x, float* __restrict__ out) {
    int i = blockIdx.x * blockDim.x + threadIdx.x;
    if (i >= NSRC_F * OUTC) return;
    int row = i / OUTC, c = i % OUTC;
    out[i] += x[(size_t)row * 98 + c];
}

// ---------------- host ----------------
static float* sym(const void* s) { void* p = nullptr; cudaGetSymbolAddress(&p, s); return (float*)p; }

extern "C" void kernel_launch(void* const* d_in, const int* in_sizes, int n_in,
                              void* d_out, int out_size) {
    const float* x        = (const float*)d_in[0];
    const int*   e2h      = (const int*)  d_in[1];
    const int*   h2h      = (const int*)  d_in[2];
    const int*   h2e      = (const int*)  d_in[3];
    const float* e2h_attr = (const float*)d_in[4];
    const float* h2h_attr = (const float*)d_in[5];
    const float* h2e_attr = (const float*)d_in[6];
    const float* era_ll   = (const float*)d_in[7];
    const float* h_ll     = (const float*)d_in[8];
    const float* fm_ctx   = (const float*)d_in[9];
    const float* fm_Wsrc  = (const float*)d_in[10];
    const float* fm_Wctx  = (const float*)d_in[11];
    const float* fm_Wedge = (const float*)d_in[12];
    const float* fm_att   = (const float*)d_in[13];
    const float* fm_Wval  = (const float*)d_in[14];
    const float* bm_ctx   = (const float*)d_in[15];
    const float* bm_Wsrc  = (const float*)d_in[16];
    const float* bm_Wctx  = (const float*)d_in[17];
    const float* bm_Wedge = (const float*)d_in[18];
    const float* bm_att   = (const float*)d_in[19];
    const float* bm_Wval  = (const float*)d_in[20];
    const float* gat_W    = (const float*)d_in[21];
    const float* gat_asrc = (const float*)d_in[23];
    const float* gat_adst = (const float*)d_in[24];
    const float* gat_We   = (const float*)d_in[22];
    const float* gat_ae   = (const float*)d_in[25];
    float* out = (float*)d_out;

    float* p_xin  = sym(g_xin);
    float* p_Vf   = sym(g_Vf);
    float* p_xlat = sym(g_xlat);
    float* p_q    = sym(g_q);
    float* p_gout = sym(g_gout);
    float* p_h    = sym(g_h);
    float* p_xpc  = sym(g_xpc);
    float* p_Vb   = sym(g_Vb);
    float* p_maxd = sym(g_maxd);
    float* p_sumd = sym(g_sumd);

    const int T = 256;
    auto cdiv = [](int a, int b) { return (a + b - 1) / b; };

    k_precompute<<<1, 512>>>(fm_Wsrc, fm_Wctx, fm_Wedge, fm_att,
                             bm_Wsrc, bm_Wctx, bm_Wedge, bm_att, gat_We, gat_ae);
    k_build_xin<<<cdiv(NSRC_F * 32, T), T>>>(x, era_ll);
    k_pctx_f<<<cdiv(NDST_F, T), T>>>(fm_ctx, h_ll);

    // Vf = x_in @ fm_Wval
    k_gemm<<<dim3(cdiv(NSRC_F, 128), 2), 256>>>(p_xin, LDA_F, fm_Wval, p_Vf, NSRC_F, HID, K_F);

    k_fill<<<cdiv(NDST_F, T), T>>>(p_maxd, -1e30f, NDST_F);
    k_fill<<<cdiv(NDST_F, T), T>>>(p_sumd, 0.f, NDST_F);
    k_fwd_logits<<<cdiv(EF_TOT, T), T>>>(e2h, e2h_attr);
    k_fwd_exp<<<cdiv(EF_TOT, T), T>>>(e2h);
    k_fill<<<cdiv(NDST_F * HID, T), T>>>(p_xlat, 0.f, NDST_F * HID);
    k_fwd_scatter<<<cdiv(EF_TOT * 32, T), T>>>(e2h);

    // GAT layers
    for (int l = 0; l < 2; l++) {
        const float* hin = (l == 0) ? p_xlat : p_h;
        k_gemm<<<dim3(cdiv(NDST_F, 128), 2), 256>>>(hin, HID, gat_W + l * HID * HID, p_q,
                                                    NDST_F, HID, HID);
        k_gat_pq<<<cdiv(NDST_F * 2 * 32, T), T>>>(gat_asrc + l * 256, gat_adst + l * 256);
        k_fill<<<cdiv(NDST_F * 2, T), T>>>(p_maxd, -1e30f, NDST_F * 2);
        k_fill<<<cdiv(NDST_F * 2, T), T>>>(p_sumd, 0.f, NDST_F * 2);
        k_gat_logits<<<cdiv(EH_TOT, T), T>>>(h2h, h2h_attr, l);
        k_gat_exp<<<cdiv(EH_TOT, T), T>>>(h2h);
        k_fill<<<cdiv(NDST_F * HID, T), T>>>(p_gout, 0.f, NDST_F * HID);
        k_gat_scatter<<<cdiv(EH_TOT * 32, T), T>>>(h2h);
        if (l == 0) k_gelu<<<cdiv(NDST_F * HID, T), T>>>();
    }

    // decoder
    k_xpc<<<cdiv(NDST_F * 32, T), T>>>(h_ll);
    k_pctx_b<<<cdiv(NSRC_F, T), T>>>(bm_ctx, era_ll);
    k_gemm<<<dim3(cdiv(NDST_F, 128), 1), 256>>>(p_xpc, K_B, bm_Wval, p_Vb, NDST_F, OUTC, K_B);

    k_fill<<<cdiv(NSRC_F, T), T>>>(p_maxd, -1e30f, NSRC_F);
    k_fill<<<cdiv(NSRC_F, T), T>>>(p_sumd, 0.f, NSRC_F);
    k_bwd_logits<<<cdiv(EF_TOT, T), T>>>(h2e, h2e_attr);
    k_bwd_exp<<<cdiv(EF_TOT, T), T>>>(h2e);
    k_fill<<<cdiv(NSRC_F * OUTC, T), T>>>(out, 0.f, NSRC_F * OUTC);
    k_bwd_scatter<<<cdiv(EF_TOT * 32, T), T>>>(h2e, out);
    k_final<<<cdiv(NSRC_F * OUTC, T), T>>>(x, out);
}

// round 3
// speedup vs baseline: 1.1844x; 1.1844x over previous
#include <cuda_runtime.h>
#include <cuda_bf16.h>
#include <math.h>

#define BSZ    2
#define ERA    35718
#define HMESH  10242
#define NSRC_F (BSZ*ERA)      // 71436
#define NDST_F (BSZ*HMESH)    // 20484
#define E_E2H  107154
#define E_H2H  61440
#define E_H2E  107154
#define HID    256
#define K_F    102
#define LDA_F  104
#define K_B    260
#define OUTC   96
#define EF_TOT (BSZ*E_E2H)    // 214308
#define EH_TOT (BSZ*E_H2H)    // 122880

// offsets into g_wred (precomputed attention-reduced weight vectors)
#define OFF_WSA_F 0     // 102
#define OFF_WCA_F 104   // 5
#define OFF_WEA_F 112   // 3
#define OFF_WSA_B 128   // 260
#define OFF_WCA_B 392   // 5
#define OFF_WEA_B 400   // 3
#define OFF_WER   408   // 12 : (l*2+h)*4 + k

// ---------------- scratch (static device arrays; no allocation) ----------------
__device__ float g_xin  [NSRC_F*LDA_F];
__device__ float g_Vf   [NSRC_F*HID];
__device__ float g_psrc_f[NSRC_F];
__device__ float g_pctx_f[NDST_F];
__device__ float g_pqs  [NDST_F*2];
__device__ float g_pqd  [NDST_F*2];
__device__ float g_psrc_b[NDST_F];
__device__ float g_pctx_b[NSRC_F];
__device__ float g_maxd [NSRC_F];
__device__ float g_sumd [NSRC_F];
__device__ float g_expv [EH_TOT*2];      // 245760 >= 214308 too
__device__ float g_xlat [NDST_F*HID];
__device__ float g_q    [NDST_F*HID];
__device__ float g_gout [NDST_F*HID];
__device__ float g_h    [NDST_F*HID];
__device__ float g_xpc  [NDST_F*K_B];
__device__ float g_Vb   [NDST_F*OUTC];
__device__ float g_wred [512];

// ---------------- helpers ----------------
__device__ __forceinline__ void atomicMaxFloat(float* addr, float v) {
    int* ia = (int*)addr;
    int old = *ia;
    while (__int_as_float(old) < v) {
        int assumed = old;
        old = atomicCAS(ia, assumed, __float_as_int(v));
        if (old == assumed) break;
    }
}

__device__ __forceinline__ void red_add4(float* p, float a, float b, float c, float d) {
    asm volatile("red.global.add.v4.f32 [%0], {%1,%2,%3,%4};"
                 :: "l"(p), "f"(a), "f"(b), "f"(c), "f"(d) : "memory");
}

// packed f32x2 FMA (full-rate fp32 path on sm_100a; ptxas won't emit from C++)
__device__ __forceinline__ void ffma2(unsigned long long &acc, unsigned long long a2,
                                      unsigned long long b2) {
    asm volatile("fma.rn.f32x2 %0, %1, %2, %0;" : "+l"(acc) : "l"(a2), "l"(b2));
}
__device__ __forceinline__ unsigned long long pack2(float x, float y) {
    unsigned long long r;
    asm("mov.b64 %0, {%1, %2};" : "=l"(r) : "f"(x), "f"(y));
    return r;
}
__device__ __forceinline__ float2 unpack2(unsigned long long v) {
    float2 r;
    asm("mov.b64 {%0, %1}, %2;" : "=f"(r.x), "=f"(r.y) : "l"(v));
    return r;
}

__global__ void k_fill(float* p, float v, int n) {
    int i = blockIdx.x * blockDim.x + threadIdx.x;
    if (i < n) p[i] = v;
}

// ---------------- precompute reduced weight vectors ----------------
__global__ void k_precompute(const float* fmWsrc, const float* fmWctx, const float* fmWedge,
                             const float* fmAtt,
                             const float* bmWsrc, const float* bmWctx, const float* bmWedge,
                             const float* bmAtt,
                             const float* gatWe, const float* gatAe) {
    int t = threadIdx.x;  // 512 threads
    if (t < K_F) {
        float a = 0.f;
        for (int j = 0; j < HID; j++) a += fmWsrc[t*HID + j] * fmAtt[j];
        g_wred[OFF_WSA_F + t] = a;
    } else if (t < K_F + 5) {
        int r = t - K_F; float a = 0.f;
        for (int j = 0; j < HID; j++) a += fmWctx[r*HID + j] * fmAtt[j];
        g_wred[OFF_WCA_F + r] = a;
    } else if (t < K_F + 8) {
        int r = t - K_F - 5; float a = 0.f;
        for (int j = 0; j < HID; j++) a += fmWedge[r*HID + j] * fmAtt[j];
        g_wred[OFF_WEA_F + r] = a;
    }
    if (t >= 128 && t < 128 + K_B) {
        int r = t - 128; float a = 0.f;
        for (int j = 0; j < OUTC; j++) a += bmWsrc[r*OUTC + j] * bmAtt[j];
        g_wred[OFF_WSA_B + r] = a;
    }
    if (t >= 400 && t < 405) {
        int r = t - 400; float a = 0.f;
        for (int j = 0; j < OUTC; j++) a += bmWctx[r*OUTC + j] * bmAtt[j];
        g_wred[OFF_WCA_B + r] = a;
    }
    if (t >= 405 && t < 408) {
        int r = t - 405; float a = 0.f;
        for (int j = 0; j < OUTC; j++) a += bmWedge[r*OUTC + j] * bmAtt[j];
        g_wred[OFF_WEA_B + r] = a;
    }
    if (t >= 408 && t < 420) {
        int idx = t - 408;
        int l = idx / 6, h = (idx % 6) / 3, k = idx % 3;
        float a = 0.f;
        for (int dd = 0; dd < 128; dd++)
            a += gatWe[((l*3 + k)*2 + h)*128 + dd] * gatAe[(l*2 + h)*128 + dd];
        g_wred[OFF_WER + (l*2 + h)*4 + k] = a;
    }
}

// ---------------- build x_in (concat + pad) and psrc_f ----------------
__global__ void k_build_xin(const float* __restrict__ x, const float* __restrict__ era_ll) {
    int w = (blockIdx.x * blockDim.x + threadIdx.x) >> 5;
    int lane = threadIdx.x & 31;
    if (w >= NSRC_F) return;
    int node = w % ERA;
    float acc = 0.f;
#pragma unroll
    for (int it = 0; it < 4; it++) {
        int c = lane + it * 32;
        float v = 0.f;
        if (c < 98)       v = x[(size_t)w * 98 + c];
        else if (c < 102) v = era_ll[node * 4 + (c - 98)];
        if (c < LDA_F) g_xin[w * LDA_F + c] = v;
        if (c < 102)   acc += v * g_wred[OFF_WSA_F + c];
    }
    for (int o = 16; o > 0; o >>= 1) acc += __shfl_down_sync(0xffffffff, acc, o);
    if (lane == 0) g_psrc_f[w] = acc;
}

__global__ void k_pctx_f(const float* __restrict__ fm_ctx, const float* __restrict__ h_ll) {
    int d = blockIdx.x * blockDim.x + threadIdx.x;
    if (d >= NDST_F) return;
    int node = d % HMESH;
    float a = fm_ctx[node] * g_wred[OFF_WCA_F];
#pragma unroll
    for (int k = 0; k < 4; k++) a += h_ll[node * 4 + k] * g_wred[OFF_WCA_F + 1 + k];
    g_pctx_f[d] = a;
}

// ---------------- fp32 tiled GEMM (f32x2, conflict-free): C = A[M,K(lda)] * B[K,N] ----------------
__global__ __launch_bounds__(256, 2) void k_gemm(const float* __restrict__ A, int lda,
                                                 const float* __restrict__ B,
                                                 float* __restrict__ C,
                                                 int M, int N, int K) {
    __shared__ float As[16 * 128];
    __shared__ float Bs[16 * 128];
    int tid = threadIdx.x;
    int m0 = blockIdx.x * 128;
    int n0 = blockIdx.y * 128;
    int ty = tid >> 4, tx = tid & 15;

    // accumulators: 8 rows x 4 col-pairs (each pair = 2 fp32 packed)
    unsigned long long acc[8][4];
#pragma unroll
    for (int i = 0; i < 8; i++)
#pragma unroll
        for (int j = 0; j < 4; j++) acc[i][j] = 0ull;

    for (int k0 = 0; k0 < K; k0 += 16) {
        {   // load A tile (transposed into As[k][m])
            int am = tid >> 1;
            int ak = (tid & 1) * 8;
            int grow = m0 + am;
#pragma unroll
            for (int i = 0; i < 8; i++) {
                int k = k0 + ak + i;
                float v = (grow < M && k < K) ? A[(size_t)grow * lda + k] : 0.f;
                As[(ak + i) * 128 + am] = v;
            }
        }
        {   // load B tile
            int bk = tid >> 4;
            int bn = (tid & 15) * 8;
            int kg = k0 + bk;
#pragma unroll
            for (int i = 0; i < 8; i++) {
                int gn = n0 + bn + i;
                float v = (kg < K && gn < N) ? B[(size_t)kg * N + gn] : 0.f;
                Bs[bk * 128 + bn + i] = v;
            }
        }
        __syncthreads();
#pragma unroll
        for (int kk = 0; kk < 16; kk++) {
            // split 4+4 mapping: contiguous 16B runs -> conflict-free LDS.128
            float4 a0 = *(const float4*)&As[kk * 128 + ty * 4];
            float4 a1 = *(const float4*)&As[kk * 128 + 64 + ty * 4];
            float4 b0 = *(const float4*)&Bs[kk * 128 + tx * 4];
            float4 b1 = *(const float4*)&Bs[kk * 128 + 64 + tx * 4];
            unsigned long long bp[4] = {pack2(b0.x, b0.y), pack2(b0.z, b0.w),
                                        pack2(b1.x, b1.y), pack2(b1.z, b1.w)};
            float av[8] = {a0.x, a0.y, a0.z, a0.w, a1.x, a1.y, a1.z, a1.w};
#pragma unroll
            for (int i = 0; i < 8; i++) {
                unsigned long long aa = pack2(av[i], av[i]);
#pragma unroll
                for (int j = 0; j < 4; j++) ffma2(acc[i][j], aa, bp[j]);
            }
        }
        __syncthreads();
    }

    // epilogue: rows {m0+ty*4+i, m0+64+ty*4+i}, cols {n0+tx*4.., n0+64+tx*4..}
#pragma unroll
    for (int i = 0; i < 8; i++) {
        int row = m0 + ((i < 4) ? (ty * 4 + i) : (64 + ty * 4 + (i - 4)));
        if (row >= M) continue;
#pragma unroll
        for (int half = 0; half < 2; half++) {
            int col = n0 + half * 64 + tx * 4;
            float2 lo = unpack2(acc[i][half * 2]);
            float2 hi = unpack2(acc[i][half * 2 + 1]);
            if (col + 3 < N) {
                *(float4*)&C[(size_t)row * N + col] = make_float4(lo.x, lo.y, hi.x, hi.y);
            } else {
                if (col < N)     C[(size_t)row * N + col]     = lo.x;
                if (col + 1 < N) C[(size_t)row * N + col + 1] = lo.y;
                if (col + 2 < N) C[(size_t)row * N + col + 2] = hi.x;
                if (col + 3 < N) C[(size_t)row * N + col + 3] = hi.y;
            }
        }
    }
}

// ---------------- forward mapper edge passes ----------------
__global__ void k_fwd_logits(const int* __restrict__ e2h, const float* __restrict__ ea) {
    int e = blockIdx.x * blockDim.x + threadIdx.x;
    if (e >= EF_TOT) return;
    int eo = e % E_E2H, b = e / E_E2H;
    int s = e2h[eo] + b * ERA;
    int d = e2h[E_E2H + eo] + b * HMESH;
    float pe = ea[eo*3]   * g_wred[OFF_WEA_F]
             + ea[eo*3+1] * g_wred[OFF_WEA_F+1]
             + ea[eo*3+2] * g_wred[OFF_WEA_F+2];
    float l = g_psrc_f[s] + g_pctx_f[d] + pe;
    l = l > 0.f ? l : 0.2f * l;
    g_expv[e] = l;
    atomicMaxFloat(&g_maxd[d], l);
}

__global__ void k_fwd_exp(const int* __restrict__ e2h) {
    int e = blockIdx.x * blockDim.x + threadIdx.x;
    if (e >= EF_TOT) return;
    int eo = e % E_E2H, b = e / E_E2H;
    int d = e2h[E_E2H + eo] + b * HMESH;
    float v = expf(g_expv[e] - g_maxd[d]);
    g_expv[e] = v;
    atomicAdd(&g_sumd[d], v);
}

__global__ void k_fwd_scatter(const int* __restrict__ e2h) {
    int e = (blockIdx.x * blockDim.x + threadIdx.x) >> 5;
    int lane = threadIdx.x & 31;
    if (e >= EF_TOT) return;
    int eo = e % E_E2H, b = e / E_E2H;
    int s = e2h[eo] + b * ERA;
    int d = e2h[E_E2H + eo] + b * HMESH;
    float alpha = g_expv[e] / (g_sumd[d] + 1e-9f);
    int bs = s * HID, bd = d * HID;
#pragma unroll
    for (int c = lane * 4; c < HID; c += 128) {
        float4 v = *(const float4*)&g_Vf[bs + c];
        red_add4(&g_xlat[bd + c], alpha * v.x, alpha * v.y, alpha * v.z, alpha * v.w);
    }
}

// ---------------- GAT passes ----------------
__global__ void k_gat_pq(const float* __restrict__ asrc, const float* __restrict__ adst) {
    int w = (blockIdx.x * blockDim.x + threadIdx.x) >> 5;
    int lane = threadIdx.x & 31;
    if (w >= NDST_F * 2) return;
    int n = w >> 1, h = w & 1;
    const float* qrow = &g_q[n * HID + h * 128];
    float as_ = 0.f, ad_ = 0.f;
#pragma unroll
    for (int it = 0; it < 4; it++) {
        int dd = lane + it * 32;
        float qv = qrow[dd];
        as_ += qv * asrc[h * 128 + dd];
        ad_ += qv * adst[h * 128 + dd];
    }
    for (int o = 16; o > 0; o >>= 1) {
        as_ += __shfl_down_sync(0xffffffff, as_, o);
        ad_ += __shfl_down_sync(0xffffffff, ad_, o);
    }
    if (lane == 0) { g_pqs[w] = as_; g_pqd[w] = ad_; }
}

__global__ void k_gat_logits(const int* __restrict__ h2h, const float* __restrict__ ea, int l) {
    int e = blockIdx.x * blockDim.x + threadIdx.x;
    if (e >= EH_TOT) return;
    int eo = e % E_H2H, b = e / E_H2H;
    int s = h2h[eo] + b * HMESH;
    int d = h2h[E_H2H + eo] + b * HMESH;
#pragma unroll
    for (int h = 0; h < 2; h++) {
        const float* wer = &g_wred[OFF_WER + (l*2 + h)*4];
        float pe = ea[eo*3]*wer[0] + ea[eo*3+1]*wer[1] + ea[eo*3+2]*wer[2];
        float lg = g_pqs[s*2 + h] + g_pqd[d*2 + h] + pe;
        lg = lg > 0.f ? lg : 0.2f * lg;
        g_expv[e*2 + h] = lg;
        atomicMaxFloat(&g_maxd[d*2 + h], lg);
    }
}

__global__ void k_gat_exp(const int* __restrict__ h2h) {
    int e = blockIdx.x * blockDim.x + threadIdx.x;
    if (e >= EH_TOT) return;
    int eo = e % E_H2H, b = e / E_H2H;
    int d = h2h[E_H2H + eo] + b * HMESH;
#pragma unroll
    for (int h = 0; h < 2; h++) {
        float v = expf(g_expv[e*2 + h] - g_maxd[d*2 + h]);
        g_expv[e*2 + h] = v;
        atomicAdd(&g_sumd[d*2 + h], v);
    }
}

__global__ void k_gat_scatter(const int* __restrict__ h2h) {
    int e = (blockIdx.x * blockDim.x + threadIdx.x) >> 5;
    int lane = threadIdx.x & 31;
    if (e >= EH_TOT) return;
    int eo = e % E_H2H, b = e / E_H2H;
    int s = h2h[eo] + b * HMESH;
    int d = h2h[E_H2H + eo] + b * HMESH;
    float a0 = g_expv[e*2]     / (g_sumd[d*2]     + 1e-9f);
    float a1 = g_expv[e*2 + 1] / (g_sumd[d*2 + 1] + 1e-9f);
    int bs = s * HID, bd = d * HID;
#pragma unroll
    for (int c = lane * 4; c < HID; c += 128) {
        float alpha = (c < 128) ? a0 : a1;
        float4 v = *(const float4*)&g_q[bs + c];
        red_add4(&g_gout[bd + c], alpha * v.x, alpha * v.y, alpha * v.z, alpha * v.w);
    }
}

__global__ void k_gelu() {
    int i = blockIdx.x * blockDim.x + threadIdx.x;
    if (i >= NDST_F * HID) return;
    float x = g_gout[i];
    float t = tanhf(0.7978845608f * (x + 0.044715f * x * x * x));
    g_h[i] = 0.5f * x * (1.f + t);
}

// ---------------- decoder prep ----------------
__global__ void k_xpc(const float* __restrict__ h_ll) {
    int n = (blockIdx.x * blockDim.x + threadIdx.x) >> 5;
    int lane = threadIdx.x & 31;
    if (n >= NDST_F) return;
    int node = n % HMESH;
    float acc = 0.f;
#pragma unroll
    for (int it = 0; it < 9; it++) {
        int c = lane + it * 32;
        if (c < K_B) {
            float v;
            if (c < 256) v = g_gout[n * HID + c] + g_xlat[n * HID + c];
            else         v = h_ll[node * 4 + (c - 256)];
            g_xpc[n * K_B + c] = v;
            acc += v * g_wred[OFF_WSA_B + c];
        }
    }
    for (int o = 16; o > 0; o >>= 1) acc += __shfl_down_sync(0xffffffff, acc, o);
    if (lane == 0) g_psrc_b[n] = acc;
}

__global__ void k_pctx_b(const float* __restrict__ bm_ctx, const float* __restrict__ era_ll) {
    int d = blockIdx.x * blockDim.x + threadIdx.x;
    if (d >= NSRC_F) return;
    int node = d % ERA;
    float a = bm_ctx[node] * g_wred[OFF_WCA_B];
#pragma unroll
    for (int k = 0; k < 4; k++) a += era_ll[node * 4 + k] * g_wred[OFF_WCA_B + 1 + k];
    g_pctx_b[d] = a;
}

__global__ void k_bwd_logits(const int* __restrict__ h2e, const float* __restrict__ ea) {
    int e = blockIdx.x * blockDim.x + threadIdx.x;
    if (e >= EF_TOT) return;
    int eo = e % E_H2E, b = e / E_H2E;
    int s = h2e[eo] + b * HMESH;
    int d = h2e[E_H2E + eo] + b * ERA;
    float pe = ea[eo*3]   * g_wred[OFF_WEA_B]
             + ea[eo*3+1] * g_wred[OFF_WEA_B+1]
             + ea[eo*3+2] * g_wred[OFF_WEA_B+2];
    float l = g_psrc_b[s] + g_pctx_b[d] + pe;
    l = l > 0.f ? l : 0.2f * l;
    g_expv[e] = l;
    atomicMaxFloat(&g_maxd[d], l);
}

__global__ void k_bwd_exp(const int* __restrict__ h2e) {
    int e = blockIdx.x * blockDim.x + threadIdx.x;
    if (e >= EF_TOT) return;
    int eo = e % E_H2E, b = e / E_H2E;
    int d = h2e[E_H2E + eo] + b * ERA;
    float v = expf(g_expv[e] - g_maxd[d]);
    g_expv[e] = v;
    atomicAdd(&g_sumd[d], v);
}

__global__ void k_bwd_scatter(const int* __restrict__ h2e, float* __restrict__ out) {
    int e = (blockIdx.x * blockDim.x + threadIdx.x) >> 5;
    int lane = threadIdx.x & 31;
    if (e >= EF_TOT) return;
    int eo = e % E_H2E, b = e / E_H2E;
    int s = h2e[eo] + b * HMESH;
    int d = h2e[E_H2E + eo] + b * ERA;
    float alpha = g_expv[e] / (g_sumd[d] + 1e-9f);
    int c = lane * 4;
    if (c < OUTC) {
        float4 v = *(const float4*)&g_Vb[s * OUTC + c];
        red_add4(&out[d * OUTC + c], alpha * v.x, alpha * v.y, alpha * v.z, alpha * v.w);
    }
}

__global__ void k_final(const float* __restrict__ x, float* __restrict__ out) {
    int i = blockIdx.x * blockDim.x + threadIdx.x;
    if (i >= NSRC_F * OUTC) return;
    int row = i / OUTC, c = i % OUTC;
    out[i] += x[(size_t)row * 98 + c];
}

// ---------------- host ----------------
static float* sym(const void* s) { void* p = nullptr; cudaGetSymbolAddress(&p, s); return (float*)p; }

extern "C" void kernel_launch(void* const* d_in, const int* in_sizes, int n_in,
                              void* d_out, int out_size) {
    const float* x        = (const float*)d_in[0];
    const int*   e2h      = (const int*)  d_in[1];
    const int*   h2h      = (const int*)  d_in[2];
    const int*   h2e      = (const int*)  d_in[3];
    const float* e2h_attr = (const float*)d_in[4];
    const float* h2h_attr = (const float*)d_in[5];
    const float* h2e_attr = (const float*)d_in[6];
    const float* era_ll   = (const float*)d_in[7];
    const float* h_ll     = (const float*)d_in[8];
    const float* fm_ctx   = (const float*)d_in[9];
    const float* fm_Wsrc  = (const float*)d_in[10];
    const float* fm_Wctx  = (const float*)d_in[11];
    const float* fm_Wedge = (const float*)d_in[12];
    const float* fm_att   = (const float*)d_in[13];
    const float* fm_Wval  = (const float*)d_in[14];
    const float* bm_ctx   = (const float*)d_in[15];
    const float* bm_Wsrc  = (const float*)d_in[16];
    const float* bm_Wctx  = (const float*)d_in[17];
    const float* bm_Wedge = (const float*)d_in[18];
    const float* bm_att   = (const float*)d_in[19];
    const float* bm_Wval  = (const float*)d_in[20];
    const float* gat_W    = (const float*)d_in[21];
    const float* gat_asrc = (const float*)d_in[23];
    const float* gat_adst = (const float*)d_in[24];
    const float* gat_We   = (const float*)d_in[22];
    const float* gat_ae   = (const float*)d_in[25];
    float* out = (float*)d_out;

    float* p_xin  = sym(g_xin);
    float* p_Vf   = sym(g_Vf);
    float* p_xlat = sym(g_xlat);
    float* p_q    = sym(g_q);
    float* p_gout = sym(g_gout);
    float* p_h    = sym(g_h);
    float* p_xpc  = sym(g_xpc);
    float* p_Vb   = sym(g_Vb);
    float* p_maxd = sym(g_maxd);
    float* p_sumd = sym(g_sumd);

    const int T = 256;
    auto cdiv = [](int a, int b) { return (a + b - 1) / b; };

    k_precompute<<<1, 512>>>(fm_Wsrc, fm_Wctx, fm_Wedge, fm_att,
                             bm_Wsrc, bm_Wctx, bm_Wedge, bm_att, gat_We, gat_ae);
    k_build_xin<<<cdiv(NSRC_F * 32, T), T>>>(x, era_ll);
    k_pctx_f<<<cdiv(NDST_F, T), T>>>(fm_ctx, h_ll);

    // Vf = x_in @ fm_Wval
    k_gemm<<<dim3(cdiv(NSRC_F, 128), 2), 256>>>(p_xin, LDA_F, fm_Wval, p_Vf, NSRC_F, HID, K_F);

    k_fill<<<cdiv(NDST_F, T), T>>>(p_maxd, -1e30f, NDST_F);
    k_fill<<<cdiv(NDST_F, T), T>>>(p_sumd, 0.f, NDST_F);
    k_fwd_logits<<<cdiv(EF_TOT, T), T>>>(e2h, e2h_attr);
    k_fwd_exp<<<cdiv(EF_TOT, T), T>>>(e2h);
    k_fill<<<cdiv(NDST_F * HID, T), T>>>(p_xlat, 0.f, NDST_F * HID);
    k_fwd_scatter<<<cdiv(EF_TOT * 32, T), T>>>(e2h);

    // GAT layers
    for (int l = 0; l < 2; l++) {
        const float* hin = (l == 0) ? p_xlat : p_h;
        k_gemm<<<dim3(cdiv(NDST_F, 128), 2), 256>>>(hin, HID, gat_W + l * HID * HID, p_q,
                                                    NDST_F, HID, HID);
        k_gat_pq<<<cdiv(NDST_F * 2 * 32, T), T>>>(gat_asrc + l * 256, gat_adst + l * 256);
        k_fill<<<cdiv(NDST_F * 2, T), T>>>(p_maxd, -1e30f, NDST_F * 2);
        k_fill<<<cdiv(NDST_F * 2, T), T>>>(p_sumd, 0.f, NDST_F * 2);
        k_gat_logits<<<cdiv(EH_TOT, T), T>>>(h2h, h2h_attr, l);
        k_gat_exp<<<cdiv(EH_TOT, T), T>>>(h2h);
        k_fill<<<cdiv(NDST_F * HID, T), T>>>(p_gout, 0.f, NDST_F * HID);
        k_gat_scatter<<<cdiv(EH_TOT * 32, T), T>>>(h2h);
        if (l == 0) k_gelu<<<cdiv(NDST_F * HID, T), T>>>();
    }

    // decoder
    k_xpc<<<cdiv(NDST_F * 32, T), T>>>(h_ll);
    k_pctx_b<<<cdiv(NSRC_F, T), T>>>(bm_ctx, era_ll);
    k_gemm<<<dim3(cdiv(NDST_F, 128), 1), 256>>>(p_xpc, K_B, bm_Wval, p_Vb, NDST_F, OUTC, K_B);

    k_fill<<<cdiv(NSRC_F, T), T>>>(p_maxd, -1e30f, NSRC_F);
    k_fill<<<cdiv(NSRC_F, T), T>>>(p_sumd, 0.f, NSRC_F);
    k_bwd_logits<<<cdiv(EF_TOT, T), T>>>(h2e, h2e_attr);
    k_bwd_exp<<<cdiv(EF_TOT, T), T>>>(h2e);
    k_fill<<<cdiv(NSRC_F * OUTC, T), T>>>(out, 0.f, NSRC_F * OUTC);
    k_bwd_scatter<<<cdiv(EF_TOT * 32, T), T>>>(h2e, out);
    k_final<<<cdiv(NSRC_F * OUTC, T), T>>>(x, out);
}